// round 3
// baseline (speedup 1.0000x reference)
#include <cuda_runtime.h>
#include <math.h>

#define BB 16
#define NN 1024
#define HH 256
#define FIN 64
#define NEGV (-9e15f)

// Scratch (device globals: no allocation allowed in kernel_launch)
__device__ float g_x[BB*NN*HH];   // 16 MB
__device__ float g_h[BB*NN*HH];   // 16 MB
__device__ float g_s1[BB*NN];
__device__ float g_s2[BB*NN];

// out[r, 0:256] = x[r, 0:K] @ W[K,256] (+ bias). 16 rows per block, 256 threads.
template<int K, bool BIAS>
__global__ void mm_k(const float* __restrict__ x, const float* __restrict__ W,
                     const float* __restrict__ bias, float* __restrict__ out) {
    __shared__ float Ws[32][HH];
    __shared__ float xs[16][32];
    const int t = threadIdx.x;
    const int r0 = blockIdx.x * 16;
    float acc[16];
#pragma unroll
    for (int i = 0; i < 16; i++) acc[i] = 0.f;

    for (int kc = 0; kc < K; kc += 32) {
#pragma unroll 8
        for (int kk = 0; kk < 32; kk++) Ws[kk][t] = W[(kc + kk) * HH + t];
#pragma unroll
        for (int l = 0; l < 2; l++) {
            int idx = t + l * 256;
            xs[idx >> 5][idx & 31] = x[(r0 + (idx >> 5)) * K + kc + (idx & 31)];
        }
        __syncthreads();
#pragma unroll
        for (int kk = 0; kk < 32; kk += 4) {
            float w0 = Ws[kk][t], w1 = Ws[kk + 1][t], w2 = Ws[kk + 2][t], w3 = Ws[kk + 3][t];
#pragma unroll
            for (int i = 0; i < 16; i++) {
                float4 xv = *reinterpret_cast<const float4*>(&xs[i][kk]);
                acc[i] = fmaf(xv.x, w0, fmaf(xv.y, w1, fmaf(xv.z, w2, fmaf(xv.w, w3, acc[i]))));
            }
        }
        __syncthreads();
    }
    float bv = BIAS ? bias[t] : 0.f;
#pragma unroll
    for (int i = 0; i < 16; i++) out[(r0 + i) * HH + t] = acc[i] + bv;
}

// s1[r] = h[r,:]@a1 ; s2[r] = h[r,:]@a2. One warp per row, 8 rows/block.
__global__ void sdot_k(const float* __restrict__ h, const float* __restrict__ a1,
                       const float* __restrict__ a2, float* __restrict__ s1,
                       float* __restrict__ s2) {
    const int warp = threadIdx.x >> 5, lane = threadIdx.x & 31;
    const int row = blockIdx.x * 8 + warp;
    const float* hr = h + row * HH;
    float acc1 = 0.f, acc2 = 0.f;
#pragma unroll
    for (int c = lane; c < HH; c += 32) {
        float hv = hr[c];
        acc1 = fmaf(hv, a1[c], acc1);
        acc2 = fmaf(hv, a2[c], acc2);
    }
#pragma unroll
    for (int off = 16; off; off >>= 1) {
        acc1 += __shfl_xor_sync(~0u, acc1, off);
        acc2 += __shfl_xor_sync(~0u, acc2, off);
    }
    if (lane == 0) { s1[row] = acc1; s2[row] = acc2; }
}

// Fused masked-softmax attention + aggregation + relu.
// out[b,i,:] = relu( softmax_j( mask ? leaky(s1[i]+s2[j]) : NEG ) @ h[b,:,:] )
// 8 rows (i) per block; 256 threads; weights kept in SMEM.
__global__ void attn_k(const float* __restrict__ h, const float* __restrict__ adj,
                       const float* __restrict__ s1, const float* __restrict__ s2,
                       float* __restrict__ out) {
    __shared__ float s2s[NN];
    __shared__ float wsh[8][NN];
    __shared__ float s1s[8];
    __shared__ float red[8][8];
    __shared__ float msh[8];
    __shared__ float ssh[8];
    const int t = threadIdx.x, lane = t & 31, warp = t >> 5;
    const int b = blockIdx.y, r0 = blockIdx.x * 8;

    const float* s2b = s2 + b * NN;
#pragma unroll
    for (int q = 0; q < 4; q++) s2s[t + q * 256] = s2b[t + q * 256];
    if (t < 8) s1s[t] = s1[b * NN + r0 + t];
    __syncthreads();

    const float* adjb = adj + ((size_t)b * NN + r0) * NN;

    // Phase A: masked leaky scores + per-row max (adj read exactly once)
    float lmax[8];
#pragma unroll
    for (int i = 0; i < 8; i++) {
        float s1v = s1s[i];
        float lm = -3.4e38f;
#pragma unroll
        for (int q = 0; q < 4; q++) {
            int j = t + q * 256;
            float a = adjb[i * NN + j];
            float z = s1v + s2s[j];
            float e = (a > 0.f) ? (z >= 0.f ? z : 0.2f * z) : NEGV;
            wsh[i][j] = e;
            lm = fmaxf(lm, e);
        }
        lmax[i] = lm;
    }
#pragma unroll
    for (int i = 0; i < 8; i++) {
        float v = lmax[i];
#pragma unroll
        for (int off = 16; off; off >>= 1) v = fmaxf(v, __shfl_xor_sync(~0u, v, off));
        if (lane == 0) red[i][warp] = v;
    }
    __syncthreads();
    if (t < 8) {
        float m = red[t][0];
#pragma unroll
        for (int w = 1; w < 8; w++) m = fmaxf(m, red[t][w]);
        msh[t] = m;
    }
    __syncthreads();

    // Phase B: exp & row sums (SMEM only)
    float lsum[8];
#pragma unroll
    for (int i = 0; i < 8; i++) {
        float m = msh[i];
        float ls = 0.f;
#pragma unroll
        for (int q = 0; q < 4; q++) {
            int j = t + q * 256;
            float wv = expf(wsh[i][j] - m);
            wsh[i][j] = wv;
            ls += wv;
        }
        lsum[i] = ls;
    }
#pragma unroll
    for (int i = 0; i < 8; i++) {
        float v = lsum[i];
#pragma unroll
        for (int off = 16; off; off >>= 1) v += __shfl_xor_sync(~0u, v, off);
        if (lane == 0) red[i][warp] = v;
    }
    __syncthreads();
    if (t < 8) {
        float s = 0.f;
#pragma unroll
        for (int w = 0; w < 8; w++) s += red[t][w];
        ssh[t] = s;
    }
    __syncthreads();

    // Phase C: aggregation  acc[i] = sum_j w[i][j] * h[b,j,t]
    float acc[8];
#pragma unroll
    for (int i = 0; i < 8; i++) acc[i] = 0.f;
    const float* hb = h + b * NN * HH;
    for (int j0 = 0; j0 < NN; j0 += 4) {
        float h0 = hb[(j0    ) * HH + t];
        float h1 = hb[(j0 + 1) * HH + t];
        float h2 = hb[(j0 + 2) * HH + t];
        float h3 = hb[(j0 + 3) * HH + t];
#pragma unroll
        for (int i = 0; i < 8; i++) {
            float4 wv = *reinterpret_cast<const float4*>(&wsh[i][j0]);
            acc[i] = fmaf(wv.x, h0, fmaf(wv.y, h1, fmaf(wv.z, h2, fmaf(wv.w, h3, acc[i]))));
        }
    }
#pragma unroll
    for (int i = 0; i < 8; i++) {
        float inv = 1.0f / ssh[i];
        out[(b * NN + r0 + i) * HH + t] = fmaxf(acc[i] * inv, 0.f);
    }
}

// g = relu((mean+max pooled x) @ W1 + b1) @ W2 + b2. One block per batch.
__global__ void pool_k(const float* __restrict__ x, const float* __restrict__ W1,
                       const float* __restrict__ b1, const float* __restrict__ W2,
                       const float* __restrict__ b2, float* __restrict__ g) {
    __shared__ float g0s[HH];
    __shared__ float g1s[HH];
    const int t = threadIdx.x, b = blockIdx.x;
    const float* xb = x + b * NN * HH;
    float sum = 0.f, mx = -3.4e38f;
    for (int n = 0; n < NN; n++) {
        float v = xb[n * HH + t];
        sum += v;
        mx = fmaxf(mx, v);
    }
    g0s[t] = sum * (1.0f / NN) + mx;
    __syncthreads();
    float acc = b1[t];
#pragma unroll 8
    for (int k = 0; k < HH; k++) acc = fmaf(g0s[k], W1[k * HH + t], acc);
    g1s[t] = fmaxf(acc, 0.f);
    __syncthreads();
    float acc2 = b2[t];
#pragma unroll 8
    for (int k = 0; k < HH; k++) acc2 = fmaf(g1s[k], W2[k * HH + t], acc2);
    g[b * HH + t] = acc2;
}

extern "C" void kernel_launch(void* const* d_in, const int* in_sizes, int n_in,
                              void* d_out, int out_size) {
    const float* nf   = (const float*)d_in[0];
    const float* adj  = (const float*)d_in[1];
    const float* embW = (const float*)d_in[2];
    const float* embB = (const float*)d_in[3];
    const float* W0   = (const float*)d_in[4];
    const float* a1_0 = (const float*)d_in[5];
    const float* a2_0 = (const float*)d_in[6];
    const float* W1   = (const float*)d_in[7];
    const float* a1_1 = (const float*)d_in[8];
    const float* a2_1 = (const float*)d_in[9];
    const float* gW1  = (const float*)d_in[10];
    const float* gb1  = (const float*)d_in[11];
    const float* gW2  = (const float*)d_in[12];
    const float* gb2  = (const float*)d_in[13];
    float* out = (float*)d_out;

    float *xbuf, *hbuf, *s1, *s2;
    cudaGetSymbolAddress((void**)&xbuf, g_x);
    cudaGetSymbolAddress((void**)&hbuf, g_h);
    cudaGetSymbolAddress((void**)&s1, g_s1);
    cudaGetSymbolAddress((void**)&s2, g_s2);

    const int ROWS = BB * NN;

    // embed
    mm_k<FIN, true><<<ROWS / 16, 256>>>(nf, embW, embB, xbuf);
    // GAT layer 0
    mm_k<HH, false><<<ROWS / 16, 256>>>(xbuf, W0, nullptr, hbuf);
    sdot_k<<<ROWS / 8, 256>>>(hbuf, a1_0, a2_0, s1, s2);
    attn_k<<<dim3(NN / 8, BB), 256>>>(hbuf, adj, s1, s2, xbuf);
    // GAT layer 1 (attention output -> d_out x-region directly)
    mm_k<HH, false><<<ROWS / 16, 256>>>(xbuf, W1, nullptr, hbuf);
    sdot_k<<<ROWS / 8, 256>>>(hbuf, a1_1, a2_1, s1, s2);
    attn_k<<<dim3(NN / 8, BB), 256>>>(hbuf, adj, s1, s2, out);
    // pooling + graph MLP -> g region after x
    pool_k<<<BB, 256>>>(out, gW1, gb1, gW2, gb2, out + BB * NN * HH);
}

// round 5
// speedup vs baseline: 1.3062x; 1.3062x over previous
#include <cuda_runtime.h>
#include <math.h>

#define BB 16
#define NN 1024
#define HH 256
#define FIN 64
#define NEGV (-9e15f)
#define TI 16   // attention rows per block

// Scratch (device globals: no allocation allowed in kernel_launch)
__device__ float g_x[BB*NN*HH];   // 16 MB
__device__ float g_h[BB*NN*HH];   // 16 MB
__device__ float g_s1[BB*NN];
__device__ float g_s2[BB*NN];

// out[r, 0:256] = x[r, 0:K] @ W[K,256] (+ bias). 16 rows per block, 256 threads.
template<int K, bool BIAS>
__global__ void mm_k(const float* __restrict__ x, const float* __restrict__ W,
                     const float* __restrict__ bias, float* __restrict__ out) {
    __shared__ float Ws[32][HH];
    __shared__ float xs[16][32];
    const int t = threadIdx.x;
    const int r0 = blockIdx.x * 16;
    float acc[16];
#pragma unroll
    for (int i = 0; i < 16; i++) acc[i] = 0.f;

    for (int kc = 0; kc < K; kc += 32) {
#pragma unroll 8
        for (int kk = 0; kk < 32; kk++) Ws[kk][t] = W[(kc + kk) * HH + t];
#pragma unroll
        for (int l = 0; l < 2; l++) {
            int idx = t + l * 256;
            xs[idx >> 5][idx & 31] = x[(r0 + (idx >> 5)) * K + kc + (idx & 31)];
        }
        __syncthreads();
#pragma unroll
        for (int kk = 0; kk < 32; kk += 4) {
            float w0 = Ws[kk][t], w1 = Ws[kk + 1][t], w2 = Ws[kk + 2][t], w3 = Ws[kk + 3][t];
#pragma unroll
            for (int i = 0; i < 16; i++) {
                float4 xv = *reinterpret_cast<const float4*>(&xs[i][kk]);
                acc[i] = fmaf(xv.x, w0, fmaf(xv.y, w1, fmaf(xv.z, w2, fmaf(xv.w, w3, acc[i]))));
            }
        }
        __syncthreads();
    }
    float bv = BIAS ? bias[t] : 0.f;
#pragma unroll
    for (int i = 0; i < 16; i++) out[(r0 + i) * HH + t] = acc[i] + bv;
}

// s1[r] = h[r,:]@a1 ; s2[r] = h[r,:]@a2. One warp per row, 8 rows/block.
__global__ void sdot_k(const float* __restrict__ h, const float* __restrict__ a1,
                       const float* __restrict__ a2, float* __restrict__ s1,
                       float* __restrict__ s2) {
    const int warp = threadIdx.x >> 5, lane = threadIdx.x & 31;
    const int row = blockIdx.x * 8 + warp;
    const float* hr = h + row * HH;
    float acc1 = 0.f, acc2 = 0.f;
#pragma unroll
    for (int c = lane; c < HH; c += 32) {
        float hv = hr[c];
        acc1 = fmaf(hv, a1[c], acc1);
        acc2 = fmaf(hv, a2[c], acc2);
    }
#pragma unroll
    for (int off = 16; off; off >>= 1) {
        acc1 += __shfl_xor_sync(~0u, acc1, off);
        acc2 += __shfl_xor_sync(~0u, acc2, off);
    }
    if (lane == 0) { s1[row] = acc1; s2[row] = acc2; }
}

// Fused masked-softmax attention + aggregation + relu.
// out[b,i,:] = relu( softmax_j( mask ? leaky(s1[i]+s2[j]) : NEG ) @ h[b,:,:] )
// TI=16 rows per block, 256 threads.
// Phase C: thread (g = t&63, s = t>>6) owns 4 h-columns [4g..4g+3] and the
// j-quarter [256s, 256s+256); partials combined via SMEM atomicAdd.
// Dynamic SMEM layout: wsh[TI][NN] | s2s[NN] | osum[TI][HH]
__global__ void __launch_bounds__(256, 2)
attn_k(const float* __restrict__ h, const float* __restrict__ adj,
       const float* __restrict__ s1, const float* __restrict__ s2,
       float* __restrict__ out) {
    extern __shared__ float smem[];
    float* wsh  = smem;                    // TI*NN
    float* s2s  = smem + TI * NN;          // NN
    float* osum = smem + TI * NN + NN;     // TI*HH
    __shared__ float red[TI][8];
    __shared__ float s1s[TI];
    __shared__ float msh[TI];
    __shared__ float ssh[TI];

    const int t = threadIdx.x, lane = t & 31, warp = t >> 5;
    const int b = blockIdx.y, r0 = blockIdx.x * TI;

    // zero the partial-sum buffer (used in epilogue)
#pragma unroll
    for (int q = 0; q < TI * HH / 256; q++) osum[t + q * 256] = 0.f;

    const float* s2b = s2 + b * NN;
#pragma unroll
    for (int q = 0; q < NN / 256; q++) s2s[t + q * 256] = s2b[t + q * 256];
    if (t < TI) s1s[t] = s1[b * NN + r0 + t];
    __syncthreads();

    const float* adjb = adj + ((size_t)b * NN + r0) * NN;

    // Phase A: masked leaky scores + per-row max (adj read exactly once)
    float lmax[TI];
#pragma unroll
    for (int i = 0; i < TI; i++) {
        float s1v = s1s[i];
        float lm = -3.4e38f;
#pragma unroll
        for (int q = 0; q < 4; q++) {
            int j = t + q * 256;
            float a = adjb[i * NN + j];
            float z = s1v + s2s[j];
            float e = (a > 0.f) ? (z >= 0.f ? z : 0.2f * z) : NEGV;
            wsh[i * NN + j] = e;
            lm = fmaxf(lm, e);
        }
        lmax[i] = lm;
    }
#pragma unroll
    for (int i = 0; i < TI; i++) {
        float v = lmax[i];
#pragma unroll
        for (int off = 16; off; off >>= 1) v = fmaxf(v, __shfl_xor_sync(~0u, v, off));
        if (lane == 0) red[i][warp] = v;
    }
    __syncthreads();
    if (t < TI) {
        float m = red[t][0];
#pragma unroll
        for (int w = 1; w < 8; w++) m = fmaxf(m, red[t][w]);
        msh[t] = m;
    }
    __syncthreads();

    // Phase B: exp & row sums (SMEM only)
    float lsum[TI];
#pragma unroll
    for (int i = 0; i < TI; i++) {
        float m = msh[i];
        float ls = 0.f;
#pragma unroll
        for (int q = 0; q < 4; q++) {
            int j = t + q * 256;
            float wv = expf(wsh[i * NN + j] - m);
            wsh[i * NN + j] = wv;
            ls += wv;
        }
        lsum[i] = ls;
    }
#pragma unroll
    for (int i = 0; i < TI; i++) {
        float v = lsum[i];
#pragma unroll
        for (int off = 16; off; off >>= 1) v += __shfl_xor_sync(~0u, v, off);
        if (lane == 0) red[i][warp] = v;
    }
    __syncthreads();
    if (t < TI) {
        float s = 0.f;
#pragma unroll
        for (int w = 0; w < 8; w++) s += red[t][w];
        ssh[t] = s;
    }
    __syncthreads();

    // Phase C: register-blocked aggregation.
    // acc4[i] (float4) = sum over this thread's j-quarter of w[i][j] * h[j][4g..4g+3]
    const int g = t & 63, s = t >> 6;
    const int jbeg = s * (NN / 4);
    const float4* hb4 = reinterpret_cast<const float4*>(h + (size_t)b * NN * HH);

    float4 acc4[TI];
#pragma unroll
    for (int i = 0; i < TI; i++) acc4[i] = make_float4(0.f, 0.f, 0.f, 0.f);

#pragma unroll 4
    for (int j = jbeg; j < jbeg + NN / 4; j += 2) {
        float4 h0 = hb4[(size_t)j * (HH / 4) + g];
        float4 h1 = hb4[(size_t)(j + 1) * (HH / 4) + g];
#pragma unroll
        for (int i = 0; i < TI; i++) {
            float2 w = *reinterpret_cast<const float2*>(&wsh[i * NN + j]);
            acc4[i].x = fmaf(w.x, h0.x, acc4[i].x);
            acc4[i].y = fmaf(w.x, h0.y, acc4[i].y);
            acc4[i].z = fmaf(w.x, h0.z, acc4[i].z);
            acc4[i].w = fmaf(w.x, h0.w, acc4[i].w);
            acc4[i].x = fmaf(w.y, h1.x, acc4[i].x);
            acc4[i].y = fmaf(w.y, h1.y, acc4[i].y);
            acc4[i].z = fmaf(w.y, h1.z, acc4[i].z);
            acc4[i].w = fmaf(w.y, h1.w, acc4[i].w);
        }
    }

    // combine the 4 j-set partials
#pragma unroll
    for (int i = 0; i < TI; i++) {
        atomicAdd(&osum[i * HH + 4 * g + 0], acc4[i].x);
        atomicAdd(&osum[i * HH + 4 * g + 1], acc4[i].y);
        atomicAdd(&osum[i * HH + 4 * g + 2], acc4[i].z);
        atomicAdd(&osum[i * HH + 4 * g + 3], acc4[i].w);
    }
    __syncthreads();

    // epilogue: normalize + relu + store
#pragma unroll
    for (int q = 0; q < TI * HH / 256; q++) {
        int idx = t + q * 256;
        int i = idx >> 8, c = idx & 255;
        float inv = 1.0f / ssh[i];
        out[((size_t)b * NN + r0 + i) * HH + c] = fmaxf(osum[idx] * inv, 0.f);
    }
}

// g = relu((mean+max pooled x) @ W1 + b1) @ W2 + b2. One block per batch.
__global__ void pool_k(const float* __restrict__ x, const float* __restrict__ W1,
                       const float* __restrict__ b1, const float* __restrict__ W2,
                       const float* __restrict__ b2, float* __restrict__ g) {
    __shared__ float g0s[HH];
    __shared__ float g1s[HH];
    const int t = threadIdx.x, b = blockIdx.x;
    const float* xb = x + b * NN * HH;
    float sum = 0.f, mx = -3.4e38f;
    for (int n = 0; n < NN; n++) {
        float v = xb[n * HH + t];
        sum += v;
        mx = fmaxf(mx, v);
    }
    g0s[t] = sum * (1.0f / NN) + mx;
    __syncthreads();
    float acc = b1[t];
#pragma unroll 8
    for (int k = 0; k < HH; k++) acc = fmaf(g0s[k], W1[k * HH + t], acc);
    g1s[t] = fmaxf(acc, 0.f);
    __syncthreads();
    float acc2 = b2[t];
#pragma unroll 8
    for (int k = 0; k < HH; k++) acc2 = fmaf(g1s[k], W2[k * HH + t], acc2);
    g[b * HH + t] = acc2;
}

extern "C" void kernel_launch(void* const* d_in, const int* in_sizes, int n_in,
                              void* d_out, int out_size) {
    const float* nf   = (const float*)d_in[0];
    const float* adj  = (const float*)d_in[1];
    const float* embW = (const float*)d_in[2];
    const float* embB = (const float*)d_in[3];
    const float* W0   = (const float*)d_in[4];
    const float* a1_0 = (const float*)d_in[5];
    const float* a2_0 = (const float*)d_in[6];
    const float* W1   = (const float*)d_in[7];
    const float* a1_1 = (const float*)d_in[8];
    const float* a2_1 = (const float*)d_in[9];
    const float* gW1  = (const float*)d_in[10];
    const float* gb1  = (const float*)d_in[11];
    const float* gW2  = (const float*)d_in[12];
    const float* gb2  = (const float*)d_in[13];
    float* out = (float*)d_out;

    float *xbuf, *hbuf, *s1, *s2;
    cudaGetSymbolAddress((void**)&xbuf, g_x);
    cudaGetSymbolAddress((void**)&hbuf, g_h);
    cudaGetSymbolAddress((void**)&s1, g_s1);
    cudaGetSymbolAddress((void**)&s2, g_s2);

    const int ROWS = BB * NN;
    const int ATTN_SMEM = (TI * NN + NN + TI * HH) * (int)sizeof(float); // 86016 B
    cudaFuncSetAttribute(attn_k, cudaFuncAttributeMaxDynamicSharedMemorySize, ATTN_SMEM);

    // embed
    mm_k<FIN, true><<<ROWS / 16, 256>>>(nf, embW, embB, xbuf);
    // GAT layer 0
    mm_k<HH, false><<<ROWS / 16, 256>>>(xbuf, W0, nullptr, hbuf);
    sdot_k<<<ROWS / 8, 256>>>(hbuf, a1_0, a2_0, s1, s2);
    attn_k<<<dim3(NN / TI, BB), 256, ATTN_SMEM>>>(hbuf, adj, s1, s2, xbuf);
    // GAT layer 1 (attention output -> d_out x-region directly)
    mm_k<HH, false><<<ROWS / 16, 256>>>(xbuf, W1, nullptr, hbuf);
    sdot_k<<<ROWS / 8, 256>>>(hbuf, a1_1, a2_1, s1, s2);
    attn_k<<<dim3(NN / TI, BB), 256, ATTN_SMEM>>>(hbuf, adj, s1, s2, out);
    // pooling + graph MLP -> g region after x
    pool_k<<<BB, 256>>>(out, gW1, gb1, gW2, gb2, out + BB * NN * HH);
}

// round 7
// speedup vs baseline: 2.0431x; 1.5641x over previous
#include <cuda_runtime.h>
#include <cstdint>
#include <math.h>

#define BB 16
#define NN 1024
#define HH 256
#define FIN 64

// ---------------- scratch ----------------
__device__ float g_x[BB*NN*HH];
__device__ float g_h[BB*NN*HH];
__device__ float g_s1[BB*NN];
__device__ float g_s2[BB*NN];

__device__ __forceinline__ uint32_t to_tf32(float x) {
    uint32_t u;
    asm("cvt.rna.tf32.f32 %0, %1;" : "=r"(u) : "f"(x));
    return u;
}
__device__ __forceinline__ void mma_tf32(float* c, const uint32_t* a, const uint32_t* bf) {
    asm volatile("mma.sync.aligned.m16n8k8.row.col.f32.tf32.tf32.f32 "
        "{%0,%1,%2,%3}, {%4,%5,%6,%7}, {%8,%9}, {%0,%1,%2,%3};"
        : "+f"(c[0]), "+f"(c[1]), "+f"(c[2]), "+f"(c[3])
        : "r"(a[0]), "r"(a[1]), "r"(a[2]), "r"(a[3]), "r"(bf[0]), "r"(bf[1]));
}

// ---------------- scalar kernels ----------------
template<int K, bool BIAS>
__global__ void mm_k(const float* __restrict__ x, const float* __restrict__ W,
                     const float* __restrict__ bias, float* __restrict__ out) {
    __shared__ float Ws[32][HH];
    __shared__ float xs[16][32];
    const int t = threadIdx.x;
    const int r0 = blockIdx.x * 16;
    float acc[16];
#pragma unroll
    for (int i = 0; i < 16; i++) acc[i] = 0.f;
    for (int kc = 0; kc < K; kc += 32) {
#pragma unroll 8
        for (int kk = 0; kk < 32; kk++) Ws[kk][t] = W[(kc + kk) * HH + t];
#pragma unroll
        for (int l = 0; l < 2; l++) {
            int idx = t + l * 256;
            xs[idx >> 5][idx & 31] = x[(r0 + (idx >> 5)) * K + kc + (idx & 31)];
        }
        __syncthreads();
#pragma unroll
        for (int kk = 0; kk < 32; kk += 4) {
            float w0 = Ws[kk][t], w1 = Ws[kk+1][t], w2 = Ws[kk+2][t], w3 = Ws[kk+3][t];
#pragma unroll
            for (int i = 0; i < 16; i++) {
                float4 xv = *reinterpret_cast<const float4*>(&xs[i][kk]);
                acc[i] = fmaf(xv.x, w0, fmaf(xv.y, w1, fmaf(xv.z, w2, fmaf(xv.w, w3, acc[i]))));
            }
        }
        __syncthreads();
    }
    float bv = BIAS ? bias[t] : 0.f;
#pragma unroll
    for (int i = 0; i < 16; i++) out[(r0 + i) * HH + t] = acc[i] + bv;
}

__global__ void sdot_k(const float* __restrict__ h, const float* __restrict__ a1,
                       const float* __restrict__ a2, float* __restrict__ s1,
                       float* __restrict__ s2) {
    const int warp = threadIdx.x >> 5, lane = threadIdx.x & 31;
    const int row = blockIdx.x * 8 + warp;
    const float* hr = h + row * HH;
    float acc1 = 0.f, acc2 = 0.f;
#pragma unroll
    for (int c = lane; c < HH; c += 32) {
        float hv = hr[c];
        acc1 = fmaf(hv, a1[c], acc1);
        acc2 = fmaf(hv, a2[c], acc2);
    }
#pragma unroll
    for (int off = 16; off; off >>= 1) {
        acc1 += __shfl_xor_sync(~0u, acc1, off);
        acc2 += __shfl_xor_sync(~0u, acc2, off);
    }
    if (lane == 0) { s1[row] = acc1; s2[row] = acc2; }
}

__global__ void pool_k(const float* __restrict__ x, const float* __restrict__ W1,
                       const float* __restrict__ b1, const float* __restrict__ W2,
                       const float* __restrict__ b2, float* __restrict__ g) {
    __shared__ float g0s[HH];
    __shared__ float g1s[HH];
    const int t = threadIdx.x, b = blockIdx.x;
    const float* xb = x + b * NN * HH;
    float sum = 0.f, mx = -3.4e38f;
    for (int n = 0; n < NN; n++) {
        float v = xb[n * HH + t];
        sum += v;
        mx = fmaxf(mx, v);
    }
    g0s[t] = sum * (1.0f / NN) + mx;
    __syncthreads();
    float acc = b1[t];
#pragma unroll 8
    for (int k = 0; k < HH; k++) acc = fmaf(g0s[k], W1[k * HH + t], acc);
    g1s[t] = fmaxf(acc, 0.f);
    __syncthreads();
    float acc2 = b2[t];
#pragma unroll 8
    for (int k = 0; k < HH; k++) acc2 = fmaf(g1s[k], W2[k * HH + t], acc2);
    g[b * HH + t] = acc2;
}

// ---------------- mma.sync tf32 fused attention ----------------
// Grid (8 i-tiles, 16 batches), 256 threads. Block computes rows [r0, r0+128).
// D[128x256]: warp w owns cols [w*32, w*32+32), all 128 rows.
//   acc[8 mtiles][4 ntiles][4] = 128 regs/thread.
// Per 32-j K-tile: P[128x32] (tf32 bits) staged in SMEM (row stride 36 ->
// fragment loads conflict-free: bank = (4*row+col)&31 hits all 32 banks).
// B fragments loaded directly from h (GMEM), one k-step lookahead.
// Softmax one-pass: m_i = leaky(s1_i + max_j s2_j) upper bound; masked -> 0.
__global__ void __launch_bounds__(256, 1)
attn_mma_k(const float* __restrict__ h, const float* __restrict__ adj,
           const float* __restrict__ s1, const float* __restrict__ s2,
           float* __restrict__ out) {
    __shared__ uint32_t Ps[128 * 36];
    __shared__ float s2f[NN];
    __shared__ float s_m[128];
    __shared__ float s_s1r[128];
    __shared__ float s_part[256];
    __shared__ float s_inv[128];
    __shared__ float s_red[8];

    const int t = threadIdx.x;
    const int wid = t >> 5, lane = t & 31;
    const int g = lane >> 2, tid4 = lane & 3;
    const int b = blockIdx.y;
    const int r0 = blockIdx.x * 128;

    // ---- s2 -> smem, block max ----
    const float* s2b = s2 + b * NN;
    float mx = -3.4e38f;
#pragma unroll
    for (int q = 0; q < 4; q++) {
        float v = s2b[t + q * 256];
        s2f[t + q * 256] = v;
        mx = fmaxf(mx, v);
    }
#pragma unroll
    for (int off = 16; off; off >>= 1) mx = fmaxf(mx, __shfl_xor_sync(~0u, mx, off));
    if (lane == 0) s_red[wid] = mx;
    __syncthreads();
    if (t == 0) {
        float m = s_red[0];
#pragma unroll
        for (int w = 1; w < 8; w++) m = fmaxf(m, s_red[w]);
        s_red[0] = m;
    }
    __syncthreads();
    const float s2max = s_red[0];
    if (t < 128) {
        float sv = s1[b * NN + r0 + t];
        s_s1r[t] = sv;
        float z = sv + s2max;
        s_m[t] = (z >= 0.f) ? z : 0.2f * z;
    }
    __syncthreads();

    // producer roles: thread t -> P row pi, j-half pth (16 cols each)
    const int pi = t >> 1, pth = t & 1;
    const float my_s1 = s_s1r[pi];
    const float my_m  = s_m[pi];
    float rsum = 0.f;

    const float* adjrow = adj + ((size_t)(b * NN + r0 + pi)) * NN;
    const float* hw = h + (size_t)b * NN * HH + wid * 32;   // this warp's 32 cols

    float acc[8][4][4];
#pragma unroll
    for (int m = 0; m < 8; m++)
#pragma unroll
        for (int n = 0; n < 4; n++)
#pragma unroll
            for (int e = 0; e < 4; e++) acc[m][n][e] = 0.f;

    float4 av[4], sv4[4];
    // preload tile 0 producer inputs
#pragma unroll
    for (int q = 0; q < 4; q++) {
        av[q]  = *reinterpret_cast<const float4*>(adjrow + pth * 16 + q * 4);
        sv4[q] = *reinterpret_cast<const float4*>(s2f + pth * 16 + q * 4);
    }

    for (int tile = 0; tile < 32; tile++) {
        const int j0 = tile * 32;

        // ---- produce P tile (mask + leaky + exp + tf32) ----
#pragma unroll
        for (int q = 0; q < 4; q++) {
            const float* a = &av[q].x;
            const float* s = &sv4[q].x;
            float p[4];
#pragma unroll
            for (int e = 0; e < 4; e++) {
                float z = my_s1 + s[e];
                float l = (z >= 0.f) ? z : 0.2f * z;
                float pv = (a[e] > 0.f) ? expf(l - my_m) : 0.f;
                rsum += pv;
                p[e] = pv;
            }
            uint4 u = make_uint4(to_tf32(p[0]), to_tf32(p[1]), to_tf32(p[2]), to_tf32(p[3]));
            *reinterpret_cast<uint4*>(&Ps[pi * 36 + pth * 16 + q * 4]) = u;
        }
        __syncthreads();

        // prefetch next tile's producer inputs (hidden behind MMA phase)
        if (tile + 1 < 32) {
            const int jn = j0 + 32;
#pragma unroll
            for (int q = 0; q < 4; q++) {
                av[q]  = *reinterpret_cast<const float4*>(adjrow + jn + pth * 16 + q * 4);
                sv4[q] = *reinterpret_cast<const float4*>(s2f + jn + pth * 16 + q * 4);
            }
        }

        // ---- MMA phase: 4 k-steps of 8 ----
        uint32_t bc[4][2], bn[4][2];
        {
            const int jr = j0;      // kstep 0 rows
#pragma unroll
            for (int n = 0; n < 4; n++) {
                bc[n][0] = to_tf32(hw[(size_t)(jr + tid4) * HH + n * 8 + g]);
                bc[n][1] = to_tf32(hw[(size_t)(jr + tid4 + 4) * HH + n * 8 + g]);
            }
        }
#pragma unroll
        for (int kk = 0; kk < 4; kk++) {
            if (kk < 3) {
                const int jr = j0 + (kk + 1) * 8;
#pragma unroll
                for (int n = 0; n < 4; n++) {
                    bn[n][0] = to_tf32(hw[(size_t)(jr + tid4) * HH + n * 8 + g]);
                    bn[n][1] = to_tf32(hw[(size_t)(jr + tid4 + 4) * HH + n * 8 + g]);
                }
            }
#pragma unroll
            for (int m = 0; m < 8; m++) {
                const int abase = (m * 16 + g) * 36 + kk * 8 + tid4;
                uint32_t a[4];
                a[0] = Ps[abase];
                a[1] = Ps[abase + 8 * 36];
                a[2] = Ps[abase + 4];
                a[3] = Ps[abase + 8 * 36 + 4];
#pragma unroll
                for (int n = 0; n < 4; n++) mma_tf32(acc[m][n], a, bc[n]);
            }
#pragma unroll
            for (int n = 0; n < 4; n++) { bc[n][0] = bn[n][0]; bc[n][1] = bn[n][1]; }
        }
        __syncthreads();
    }

    // ---- row-sum combine ----
    s_part[t] = rsum;
    __syncthreads();
    if (t < 128) s_inv[t] = 1.f / (s_part[2 * t] + s_part[2 * t + 1]);
    __syncthreads();

    // ---- epilogue: normalize + relu + store (float2 per fragment pair) ----
    float* ob = out + ((size_t)(b * NN + r0)) * HH + wid * 32;
#pragma unroll
    for (int m = 0; m < 8; m++) {
        const int rA = m * 16 + g, rB = rA + 8;
        const float invA = s_inv[rA], invB = s_inv[rB];
#pragma unroll
        for (int n = 0; n < 4; n++) {
            const int c = n * 8 + tid4 * 2;
            float2 vA = make_float2(fmaxf(acc[m][n][0] * invA, 0.f),
                                    fmaxf(acc[m][n][1] * invA, 0.f));
            float2 vB = make_float2(fmaxf(acc[m][n][2] * invB, 0.f),
                                    fmaxf(acc[m][n][3] * invB, 0.f));
            *reinterpret_cast<float2*>(ob + (size_t)rA * HH + c) = vA;
            *reinterpret_cast<float2*>(ob + (size_t)rB * HH + c) = vB;
        }
    }
}

extern "C" void kernel_launch(void* const* d_in, const int* in_sizes, int n_in,
                              void* d_out, int out_size) {
    const float* nf   = (const float*)d_in[0];
    const float* adj  = (const float*)d_in[1];
    const float* embW = (const float*)d_in[2];
    const float* embB = (const float*)d_in[3];
    const float* W0   = (const float*)d_in[4];
    const float* a1_0 = (const float*)d_in[5];
    const float* a2_0 = (const float*)d_in[6];
    const float* W1   = (const float*)d_in[7];
    const float* a1_1 = (const float*)d_in[8];
    const float* a2_1 = (const float*)d_in[9];
    const float* gW1  = (const float*)d_in[10];
    const float* gb1  = (const float*)d_in[11];
    const float* gW2  = (const float*)d_in[12];
    const float* gb2  = (const float*)d_in[13];
    float* out = (float*)d_out;

    float *xbuf, *hbuf, *s1, *s2;
    cudaGetSymbolAddress((void**)&xbuf, g_x);
    cudaGetSymbolAddress((void**)&hbuf, g_h);
    cudaGetSymbolAddress((void**)&s1, g_s1);
    cudaGetSymbolAddress((void**)&s2, g_s2);

    const int ROWS = BB * NN;

    mm_k<FIN, true><<<ROWS / 16, 256>>>(nf, embW, embB, xbuf);

    mm_k<HH, false><<<ROWS / 16, 256>>>(xbuf, W0, nullptr, hbuf);
    sdot_k<<<ROWS / 8, 256>>>(hbuf, a1_0, a2_0, s1, s2);
    attn_mma_k<<<dim3(NN / 128, BB), 256>>>(hbuf, adj, s1, s2, xbuf);

    mm_k<HH, false><<<ROWS / 16, 256>>>(xbuf, W1, nullptr, hbuf);
    sdot_k<<<ROWS / 8, 256>>>(hbuf, a1_1, a2_1, s1, s2);
    attn_mma_k<<<dim3(NN / 128, BB), 256>>>(hbuf, adj, s1, s2, out);

    pool_k<<<BB, 256>>>(out, gW1, gb1, gW2, gb2, out + BB * NN * HH);
}

// round 10
// speedup vs baseline: 2.0707x; 1.0135x over previous
#include <cuda_runtime.h>
#include <cstdint>
#include <math.h>

#define BB 16
#define NN 1024
#define HH 256
#define FIN 64

// ---------------- scratch ----------------
__device__ float g_x[BB*NN*HH];
__device__ float g_h[BB*NN*HH];
__device__ float g_s1[BB*NN];
__device__ float g_s2[BB*NN];

__device__ __forceinline__ uint32_t to_tf32(float x) {
    uint32_t u;
    asm("cvt.rna.tf32.f32 %0, %1;" : "=r"(u) : "f"(x));
    return u;
}
__device__ __forceinline__ void mma_tf32(float* c, const uint32_t* a, const uint32_t* bf) {
    asm volatile("mma.sync.aligned.m16n8k8.row.col.f32.tf32.tf32.f32 "
        "{%0,%1,%2,%3}, {%4,%5,%6,%7}, {%8,%9}, {%0,%1,%2,%3};"
        : "+f"(c[0]), "+f"(c[1]), "+f"(c[2]), "+f"(c[3])
        : "r"(a[0]), "r"(a[1]), "r"(a[2]), "r"(a[3]), "r"(bf[0]), "r"(bf[1]));
}

// ---------------- tf32 mma GEMM: out[16K x 256] = x[16K x K] @ W[K x 256] ----
// Same tiling as attn_mma_k: 128 rows/block, warp w owns cols [w*32,w*32+32).
// A tile x[128x32] staged tf32 in SMEM (stride 36, conflict-free); B = W
// fragments loaded from GMEM (L2-resident, 256KB max).
// Optional fused epilogue: bias add, and s1/s2 = h@a1, h@a2 (replaces sdot_k).
template<int K, bool BIAS, bool SDOT>
__global__ void __launch_bounds__(256, 1)
mm_mma_k(const float* __restrict__ x, const float* __restrict__ W,
         const float* __restrict__ bias,
         const float* __restrict__ a1, const float* __restrict__ a2,
         float* __restrict__ outh, float* __restrict__ s1, float* __restrict__ s2) {
    __shared__ uint32_t Ps[128 * 36];
    __shared__ float s1sh[128];
    __shared__ float s2sh[128];

    const int t = threadIdx.x;
    const int wid = t >> 5, lane = t & 31;
    const int g = lane >> 2, tid4 = lane & 3;
    const int r0 = blockIdx.x * 128;

    if (SDOT && t < 128) { s1sh[t] = 0.f; s2sh[t] = 0.f; }

    const int pi = t >> 1, pth = t & 1;          // producer: row, 16-col half
    const float* xrow = x + (size_t)(r0 + pi) * K;
    const float* Wc = W + wid * 32;

    float acc[8][4][4];
#pragma unroll
    for (int m = 0; m < 8; m++)
#pragma unroll
        for (int n = 0; n < 4; n++)
#pragma unroll
            for (int e = 0; e < 4; e++) acc[m][n][e] = 0.f;

    float4 av[4];
#pragma unroll
    for (int q = 0; q < 4; q++)
        av[q] = *reinterpret_cast<const float4*>(xrow + pth * 16 + q * 4);

    const int NKT = K / 32;
    for (int kt = 0; kt < NKT; kt++) {
        const int k0 = kt * 32;
        // stage A tile (tf32)
#pragma unroll
        for (int q = 0; q < 4; q++) {
            uint4 u = make_uint4(to_tf32(av[q].x), to_tf32(av[q].y),
                                 to_tf32(av[q].z), to_tf32(av[q].w));
            *reinterpret_cast<uint4*>(&Ps[pi * 36 + pth * 16 + q * 4]) = u;
        }
        __syncthreads();

        if (kt + 1 < NKT) {
            const int kn = k0 + 32;
#pragma unroll
            for (int q = 0; q < 4; q++)
                av[q] = *reinterpret_cast<const float4*>(xrow + kn + pth * 16 + q * 4);
        }

        uint32_t bc[4][2], bn[4][2];
#pragma unroll
        for (int n = 0; n < 4; n++) {
            bc[n][0] = to_tf32(Wc[(size_t)(k0 + tid4) * HH + n * 8 + g]);
            bc[n][1] = to_tf32(Wc[(size_t)(k0 + tid4 + 4) * HH + n * 8 + g]);
        }
#pragma unroll
        for (int kk = 0; kk < 4; kk++) {
            if (kk < 3) {
                const int kr = k0 + (kk + 1) * 8;
#pragma unroll
                for (int n = 0; n < 4; n++) {
                    bn[n][0] = to_tf32(Wc[(size_t)(kr + tid4) * HH + n * 8 + g]);
                    bn[n][1] = to_tf32(Wc[(size_t)(kr + tid4 + 4) * HH + n * 8 + g]);
                }
            }
#pragma unroll
            for (int m = 0; m < 8; m++) {
                const int abase = (m * 16 + g) * 36 + kk * 8 + tid4;
                uint32_t a[4];
                a[0] = Ps[abase];
                a[1] = Ps[abase + 8 * 36];
                a[2] = Ps[abase + 4];
                a[3] = Ps[abase + 8 * 36 + 4];
#pragma unroll
                for (int n = 0; n < 4; n++) mma_tf32(acc[m][n], a, bc[n]);
            }
#pragma unroll
            for (int n = 0; n < 4; n++) { bc[n][0] = bn[n][0]; bc[n][1] = bn[n][1]; }
        }
        __syncthreads();
    }

    // epilogue
    float2 bb[4], a1v[4], a2v[4];
#pragma unroll
    for (int n = 0; n < 4; n++) {
        const int c = wid * 32 + n * 8 + tid4 * 2;
        if (BIAS) bb[n] = *reinterpret_cast<const float2*>(bias + c);
        if (SDOT) {
            a1v[n] = *reinterpret_cast<const float2*>(a1 + c);
            a2v[n] = *reinterpret_cast<const float2*>(a2 + c);
        }
    }
    float* ob = outh + (size_t)r0 * HH + wid * 32;
#pragma unroll
    for (int m = 0; m < 8; m++) {
        const int rA = m * 16 + g, rB = rA + 8;
        float d1A = 0.f, d2A = 0.f, d1B = 0.f, d2B = 0.f;
#pragma unroll
        for (int n = 0; n < 4; n++) {
            const int c = n * 8 + tid4 * 2;
            float vA0 = acc[m][n][0] + (BIAS ? bb[n].x : 0.f);
            float vA1 = acc[m][n][1] + (BIAS ? bb[n].y : 0.f);
            float vB0 = acc[m][n][2] + (BIAS ? bb[n].x : 0.f);
            float vB1 = acc[m][n][3] + (BIAS ? bb[n].y : 0.f);
            *reinterpret_cast<float2*>(ob + (size_t)rA * HH + c) = make_float2(vA0, vA1);
            *reinterpret_cast<float2*>(ob + (size_t)rB * HH + c) = make_float2(vB0, vB1);
            if (SDOT) {
                d1A = fmaf(vA0, a1v[n].x, fmaf(vA1, a1v[n].y, d1A));
                d2A = fmaf(vA0, a2v[n].x, fmaf(vA1, a2v[n].y, d2A));
                d1B = fmaf(vB0, a1v[n].x, fmaf(vB1, a1v[n].y, d1B));
                d2B = fmaf(vB0, a2v[n].x, fmaf(vB1, a2v[n].y, d2B));
            }
        }
        if (SDOT) {
            // quad reduce (lanes g*4 .. g*4+3)
#pragma unroll
            for (int off = 1; off < 4; off <<= 1) {
                d1A += __shfl_xor_sync(~0u, d1A, off);
                d2A += __shfl_xor_sync(~0u, d2A, off);
                d1B += __shfl_xor_sync(~0u, d1B, off);
                d2B += __shfl_xor_sync(~0u, d2B, off);
            }
            if (tid4 == 0) {
                atomicAdd(&s1sh[rA], d1A);
                atomicAdd(&s2sh[rA], d2A);
                atomicAdd(&s1sh[rB], d1B);
                atomicAdd(&s2sh[rB], d2B);
            }
        }
    }
    if (SDOT) {
        __syncthreads();
        if (t < 128) { s1[r0 + t] = s1sh[t]; s2[r0 + t] = s2sh[t]; }
    }
}

// ---------------- mma.sync tf32 fused attention (unchanged from R6) ----------
__global__ void __launch_bounds__(256, 1)
attn_mma_k(const float* __restrict__ h, const float* __restrict__ adj,
           const float* __restrict__ s1, const float* __restrict__ s2,
           float* __restrict__ out) {
    __shared__ uint32_t Ps[128 * 36];
    __shared__ float s2f[NN];
    __shared__ float s_m[128];
    __shared__ float s_s1r[128];
    __shared__ float s_part[256];
    __shared__ float s_inv[128];
    __shared__ float s_red[8];

    const int t = threadIdx.x;
    const int wid = t >> 5, lane = t & 31;
    const int g = lane >> 2, tid4 = lane & 3;
    const int b = blockIdx.y;
    const int r0 = blockIdx.x * 128;

    const float* s2b = s2 + b * NN;
    float mx = -3.4e38f;
#pragma unroll
    for (int q = 0; q < 4; q++) {
        float v = s2b[t + q * 256];
        s2f[t + q * 256] = v;
        mx = fmaxf(mx, v);
    }
#pragma unroll
    for (int off = 16; off; off >>= 1) mx = fmaxf(mx, __shfl_xor_sync(~0u, mx, off));
    if (lane == 0) s_red[wid] = mx;
    __syncthreads();
    if (t == 0) {
        float m = s_red[0];
#pragma unroll
        for (int w = 1; w < 8; w++) m = fmaxf(m, s_red[w]);
        s_red[0] = m;
    }
    __syncthreads();
    const float s2max = s_red[0];
    if (t < 128) {
        float sv = s1[b * NN + r0 + t];
        s_s1r[t] = sv;
        float z = sv + s2max;
        s_m[t] = (z >= 0.f) ? z : 0.2f * z;
    }
    __syncthreads();

    const int pi = t >> 1, pth = t & 1;
    const float my_s1 = s_s1r[pi];
    const float my_m  = s_m[pi];
    float rsum = 0.f;

    const float* adjrow = adj + ((size_t)(b * NN + r0 + pi)) * NN;
    const float* hw = h + (size_t)b * NN * HH + wid * 32;

    float acc[8][4][4];
#pragma unroll
    for (int m = 0; m < 8; m++)
#pragma unroll
        for (int n = 0; n < 4; n++)
#pragma unroll
            for (int e = 0; e < 4; e++) acc[m][n][e] = 0.f;

    float4 av[4], sv4[4];
#pragma unroll
    for (int q = 0; q < 4; q++) {
        av[q]  = *reinterpret_cast<const float4*>(adjrow + pth * 16 + q * 4);
        sv4[q] = *reinterpret_cast<const float4*>(s2f + pth * 16 + q * 4);
    }

    for (int tile = 0; tile < 32; tile++) {
        const int j0 = tile * 32;
#pragma unroll
        for (int q = 0; q < 4; q++) {
            const float* a = &av[q].x;
            const float* s = &sv4[q].x;
            float p[4];
#pragma unroll
            for (int e = 0; e < 4; e++) {
                float z = my_s1 + s[e];
                float l = (z >= 0.f) ? z : 0.2f * z;
                float pv = (a[e] > 0.f) ? expf(l - my_m) : 0.f;
                rsum += pv;
                p[e] = pv;
            }
            uint4 u = make_uint4(to_tf32(p[0]), to_tf32(p[1]), to_tf32(p[2]), to_tf32(p[3]));
            *reinterpret_cast<uint4*>(&Ps[pi * 36 + pth * 16 + q * 4]) = u;
        }
        __syncthreads();

        if (tile + 1 < 32) {
            const int jn = j0 + 32;
#pragma unroll
            for (int q = 0; q < 4; q++) {
                av[q]  = *reinterpret_cast<const float4*>(adjrow + jn + pth * 16 + q * 4);
                sv4[q] = *reinterpret_cast<const float4*>(s2f + jn + pth * 16 + q * 4);
            }
        }

        uint32_t bc[4][2], bn[4][2];
#pragma unroll
        for (int n = 0; n < 4; n++) {
            bc[n][0] = to_tf32(hw[(size_t)(j0 + tid4) * HH + n * 8 + g]);
            bc[n][1] = to_tf32(hw[(size_t)(j0 + tid4 + 4) * HH + n * 8 + g]);
        }
#pragma unroll
        for (int kk = 0; kk < 4; kk++) {
            if (kk < 3) {
                const int jr = j0 + (kk + 1) * 8;
#pragma unroll
                for (int n = 0; n < 4; n++) {
                    bn[n][0] = to_tf32(hw[(size_t)(jr + tid4) * HH + n * 8 + g]);
                    bn[n][1] = to_tf32(hw[(size_t)(jr + tid4 + 4) * HH + n * 8 + g]);
                }
            }
#pragma unroll
            for (int m = 0; m < 8; m++) {
                const int abase = (m * 16 + g) * 36 + kk * 8 + tid4;
                uint32_t a[4];
                a[0] = Ps[abase];
                a[1] = Ps[abase + 8 * 36];
                a[2] = Ps[abase + 4];
                a[3] = Ps[abase + 8 * 36 + 4];
#pragma unroll
                for (int n = 0; n < 4; n++) mma_tf32(acc[m][n], a, bc[n]);
            }
#pragma unroll
            for (int n = 0; n < 4; n++) { bc[n][0] = bn[n][0]; bc[n][1] = bn[n][1]; }
        }
        __syncthreads();
    }

    s_part[t] = rsum;
    __syncthreads();
    if (t < 128) s_inv[t] = 1.f / (s_part[2 * t] + s_part[2 * t + 1]);
    __syncthreads();

    float* ob = out + ((size_t)(b * NN + r0)) * HH + wid * 32;
#pragma unroll
    for (int m = 0; m < 8; m++) {
        const int rA = m * 16 + g, rB = rA + 8;
        const float invA = s_inv[rA], invB = s_inv[rB];
#pragma unroll
        for (int n = 0; n < 4; n++) {
            const int c = n * 8 + tid4 * 2;
            float2 vA = make_float2(fmaxf(acc[m][n][0] * invA, 0.f),
                                    fmaxf(acc[m][n][1] * invA, 0.f));
            float2 vB = make_float2(fmaxf(acc[m][n][2] * invB, 0.f),
                                    fmaxf(acc[m][n][3] * invB, 0.f));
            *reinterpret_cast<float2*>(ob + (size_t)rA * HH + c) = vA;
            *reinterpret_cast<float2*>(ob + (size_t)rB * HH + c) = vB;
        }
    }
}

// ---------------- pooling + MLP ----------------
__global__ void pool_k(const float* __restrict__ x, const float* __restrict__ W1,
                       const float* __restrict__ b1, const float* __restrict__ W2,
                       const float* __restrict__ b2, float* __restrict__ g) {
    __shared__ float g0s[HH];
    __shared__ float g1s[HH];
    const int t = threadIdx.x, b = blockIdx.x;
    const float* xb = x + b * NN * HH;
    float sum = 0.f, mx = -3.4e38f;
    for (int n = 0; n < NN; n++) {
        float v = xb[n * HH + t];
        sum += v;
        mx = fmaxf(mx, v);
    }
    g0s[t] = sum * (1.0f / NN) + mx;
    __syncthreads();
    float acc = b1[t];
#pragma unroll 8
    for (int k = 0; k < HH; k++) acc = fmaf(g0s[k], W1[k * HH + t], acc);
    g1s[t] = fmaxf(acc, 0.f);
    __syncthreads();
    float acc2 = b2[t];
#pragma unroll 8
    for (int k = 0; k < HH; k++) acc2 = fmaf(g1s[k], W2[k * HH + t], acc2);
    g[b * HH + t] = acc2;
}

extern "C" void kernel_launch(void* const* d_in, const int* in_sizes, int n_in,
                              void* d_out, int out_size) {
    const float* nf   = (const float*)d_in[0];
    const float* adj  = (const float*)d_in[1];
    const float* embW = (const float*)d_in[2];
    const float* embB = (const float*)d_in[3];
    const float* W0   = (const float*)d_in[4];
    const float* a1_0 = (const float*)d_in[5];
    const float* a2_0 = (const float*)d_in[6];
    const float* W1   = (const float*)d_in[7];
    const float* a1_1 = (const float*)d_in[8];
    const float* a2_1 = (const float*)d_in[9];
    const float* gW1  = (const float*)d_in[10];
    const float* gb1  = (const float*)d_in[11];
    const float* gW2  = (const float*)d_in[12];
    const float* gb2  = (const float*)d_in[13];
    float* out = (float*)d_out;

    float *xbuf, *hbuf, *s1, *s2;
    cudaGetSymbolAddress((void**)&xbuf, g_x);
    cudaGetSymbolAddress((void**)&hbuf, g_h);
    cudaGetSymbolAddress((void**)&s1, g_s1);
    cudaGetSymbolAddress((void**)&s2, g_s2);

    const int NB = BB * NN / 128;   // 128 blocks

    // embed: x = nf @ embW + embB
    mm_mma_k<FIN, true, false><<<NB, 256>>>(nf, embW, embB, nullptr, nullptr,
                                            xbuf, nullptr, nullptr);
    // layer 0: h = x @ W0, fused s1/s2
    mm_mma_k<HH, false, true><<<NB, 256>>>(xbuf, W0, nullptr, a1_0, a2_0,
                                           hbuf, s1, s2);
    attn_mma_k<<<dim3(NN / 128, BB), 256>>>(hbuf, adj, s1, s2, xbuf);
    // layer 1
    mm_mma_k<HH, false, true><<<NB, 256>>>(xbuf, W1, nullptr, a1_1, a2_1,
                                           hbuf, s1, s2);
    attn_mma_k<<<dim3(NN / 128, BB), 256>>>(hbuf, adj, s1, s2, out);

    pool_k<<<BB, 256>>>(out, gW1, gb1, gW2, gb2, out + BB * NN * HH);
}

// round 15
// speedup vs baseline: 3.1847x; 1.5380x over previous
#include <cuda_runtime.h>
#include <cstdint>
#include <math.h>

#define BB 16
#define NN 1024
#define HH 256
#define FIN 64

// ---------------- scratch ----------------
__device__ float g_x[BB*NN*HH];
__device__ float g_h[BB*NN*HH];
__device__ float g_s1[BB*NN];
__device__ float g_s2[BB*NN];

__device__ __forceinline__ uint32_t to_tf32(float x) {
    uint32_t u;
    asm("cvt.rna.tf32.f32 %0, %1;" : "=r"(u) : "f"(x));
    return u;
}
__device__ __forceinline__ void mma_tf32(float* c, const uint32_t* a, const uint32_t* bf) {
    asm volatile("mma.sync.aligned.m16n8k8.row.col.f32.tf32.tf32.f32 "
        "{%0,%1,%2,%3}, {%4,%5,%6,%7}, {%8,%9}, {%0,%1,%2,%3};"
        : "+f"(c[0]), "+f"(c[1]), "+f"(c[2]), "+f"(c[3])
        : "r"(a[0]), "r"(a[1]), "r"(a[2]), "r"(a[3]), "r"(bf[0]), "r"(bf[1]));
}

// ---------------- tf32 mma GEMM (512 thr, warp = 16 cols) ------------------
// out[16K x 256] = x[16K x K] @ W[K x 256]; 128 rows/block, 16 warps.
// A tile x[128x32] staged tf32 in SMEM (stride 36, conflict-free).
// Fused epilogue: bias, and s1/s2 = h@a1,h@a2.
template<int K, bool BIAS, bool SDOT>
__global__ void __launch_bounds__(512, 1)
mm_mma_k(const float* __restrict__ x, const float* __restrict__ W,
         const float* __restrict__ bias,
         const float* __restrict__ a1, const float* __restrict__ a2,
         float* __restrict__ outh, float* __restrict__ s1, float* __restrict__ s2) {
    __shared__ uint32_t Ps[128 * 36];
    __shared__ float s1sh[128];
    __shared__ float s2sh[128];

    const int t = threadIdx.x;
    const int wid = t >> 5, lane = t & 31;
    const int g = lane >> 2, tid4 = lane & 3;
    const int r0 = blockIdx.x * 128;

    if (SDOT && t < 128) { s1sh[t] = 0.f; s2sh[t] = 0.f; }

    const int pi = t >> 2, pq = t & 3;           // producer: row, 8-col quarter
    const float* xrow = x + (size_t)(r0 + pi) * K;
    const float* Wc = W + wid * 16;

    float acc[8][2][4];
#pragma unroll
    for (int m = 0; m < 8; m++)
#pragma unroll
        for (int n = 0; n < 2; n++)
#pragma unroll
            for (int e = 0; e < 4; e++) acc[m][n][e] = 0.f;

    float4 av[2];
#pragma unroll
    for (int q = 0; q < 2; q++)
        av[q] = *reinterpret_cast<const float4*>(xrow + pq * 8 + q * 4);

    const int NKT = K / 32;
    for (int kt = 0; kt < NKT; kt++) {
        const int k0 = kt * 32;
#pragma unroll
        for (int q = 0; q < 2; q++) {
            uint4 u = make_uint4(to_tf32(av[q].x), to_tf32(av[q].y),
                                 to_tf32(av[q].z), to_tf32(av[q].w));
            *reinterpret_cast<uint4*>(&Ps[pi * 36 + pq * 8 + q * 4]) = u;
        }
        __syncthreads();

        if (kt + 1 < NKT) {
            const int kn = k0 + 32;
#pragma unroll
            for (int q = 0; q < 2; q++)
                av[q] = *reinterpret_cast<const float4*>(xrow + kn + pq * 8 + q * 4);
        }

        uint32_t bc[2][2], bn[2][2];
#pragma unroll
        for (int n = 0; n < 2; n++) {
            bc[n][0] = to_tf32(Wc[(size_t)(k0 + tid4) * HH + n * 8 + g]);
            bc[n][1] = to_tf32(Wc[(size_t)(k0 + tid4 + 4) * HH + n * 8 + g]);
        }
#pragma unroll
        for (int kk = 0; kk < 4; kk++) {
            if (kk < 3) {
                const int kr = k0 + (kk + 1) * 8;
#pragma unroll
                for (int n = 0; n < 2; n++) {
                    bn[n][0] = to_tf32(Wc[(size_t)(kr + tid4) * HH + n * 8 + g]);
                    bn[n][1] = to_tf32(Wc[(size_t)(kr + tid4 + 4) * HH + n * 8 + g]);
                }
            }
#pragma unroll
            for (int m = 0; m < 8; m++) {
                const int abase = (m * 16 + g) * 36 + kk * 8 + tid4;
                uint32_t a[4];
                a[0] = Ps[abase];
                a[1] = Ps[abase + 8 * 36];
                a[2] = Ps[abase + 4];
                a[3] = Ps[abase + 8 * 36 + 4];
#pragma unroll
                for (int n = 0; n < 2; n++) mma_tf32(acc[m][n], a, bc[n]);
            }
#pragma unroll
            for (int n = 0; n < 2; n++) { bc[n][0] = bn[n][0]; bc[n][1] = bn[n][1]; }
        }
        __syncthreads();
    }

    // epilogue
    float2 bb[2], a1v[2], a2v[2];
#pragma unroll
    for (int n = 0; n < 2; n++) {
        const int c = wid * 16 + n * 8 + tid4 * 2;
        if (BIAS) bb[n] = *reinterpret_cast<const float2*>(bias + c);
        if (SDOT) {
            a1v[n] = *reinterpret_cast<const float2*>(a1 + c);
            a2v[n] = *reinterpret_cast<const float2*>(a2 + c);
        }
    }
    float* ob = outh + (size_t)r0 * HH + wid * 16;
#pragma unroll
    for (int m = 0; m < 8; m++) {
        const int rA = m * 16 + g, rB = rA + 8;
        float d1A = 0.f, d2A = 0.f, d1B = 0.f, d2B = 0.f;
#pragma unroll
        for (int n = 0; n < 2; n++) {
            const int c = n * 8 + tid4 * 2;
            float vA0 = acc[m][n][0] + (BIAS ? bb[n].x : 0.f);
            float vA1 = acc[m][n][1] + (BIAS ? bb[n].y : 0.f);
            float vB0 = acc[m][n][2] + (BIAS ? bb[n].x : 0.f);
            float vB1 = acc[m][n][3] + (BIAS ? bb[n].y : 0.f);
            *reinterpret_cast<float2*>(ob + (size_t)rA * HH + c) = make_float2(vA0, vA1);
            *reinterpret_cast<float2*>(ob + (size_t)rB * HH + c) = make_float2(vB0, vB1);
            if (SDOT) {
                d1A = fmaf(vA0, a1v[n].x, fmaf(vA1, a1v[n].y, d1A));
                d2A = fmaf(vA0, a2v[n].x, fmaf(vA1, a2v[n].y, d2A));
                d1B = fmaf(vB0, a1v[n].x, fmaf(vB1, a1v[n].y, d1B));
                d2B = fmaf(vB0, a2v[n].x, fmaf(vB1, a2v[n].y, d2B));
            }
        }
        if (SDOT) {
#pragma unroll
            for (int off = 1; off < 4; off <<= 1) {
                d1A += __shfl_xor_sync(~0u, d1A, off);
                d2A += __shfl_xor_sync(~0u, d2A, off);
                d1B += __shfl_xor_sync(~0u, d1B, off);
                d2B += __shfl_xor_sync(~0u, d2B, off);
            }
            if (tid4 == 0) {
                atomicAdd(&s1sh[rA], d1A);
                atomicAdd(&s2sh[rA], d2A);
                atomicAdd(&s1sh[rB], d1B);
                atomicAdd(&s2sh[rB], d2B);
            }
        }
    }
    if (SDOT) {
        __syncthreads();
        if (t < 128) { s1[r0 + t] = s1sh[t]; s2[r0 + t] = s2sh[t]; }
    }
}

// ---------------- tf32 mma fused attention (512 thr, warp = 16 cols) --------
__global__ void __launch_bounds__(512, 1)
attn_mma_k(const float* __restrict__ h, const float* __restrict__ adj,
           const float* __restrict__ s1, const float* __restrict__ s2,
           float* __restrict__ out) {
    __shared__ uint32_t Ps[128 * 36];
    __shared__ float s2f[NN];
    __shared__ float s_m[128];
    __shared__ float s_s1r[128];
    __shared__ float s_part[512];
    __shared__ float s_inv[128];
    __shared__ float s_red[16];

    const int t = threadIdx.x;
    const int wid = t >> 5, lane = t & 31;
    const int g = lane >> 2, tid4 = lane & 3;
    const int b = blockIdx.y;
    const int r0 = blockIdx.x * 128;

    // s2 -> smem + block max
    const float* s2b = s2 + b * NN;
    float mx = -3.4e38f;
#pragma unroll
    for (int q = 0; q < 2; q++) {
        float v = s2b[t + q * 512];
        s2f[t + q * 512] = v;
        mx = fmaxf(mx, v);
    }
#pragma unroll
    for (int off = 16; off; off >>= 1) mx = fmaxf(mx, __shfl_xor_sync(~0u, mx, off));
    if (lane == 0) s_red[wid] = mx;
    __syncthreads();
    if (t == 0) {
        float m = s_red[0];
#pragma unroll
        for (int w = 1; w < 16; w++) m = fmaxf(m, s_red[w]);
        s_red[0] = m;
    }
    __syncthreads();
    const float s2max = s_red[0];
    if (t < 128) {
        float sv = s1[b * NN + r0 + t];
        s_s1r[t] = sv;
        float z = sv + s2max;
        s_m[t] = (z >= 0.f) ? z : 0.2f * z;
    }
    __syncthreads();

    const int pi = t >> 2, pq = t & 3;       // producer: row, 8-col quarter
    const float my_s1 = s_s1r[pi];
    const float my_m  = s_m[pi];
    float rsum = 0.f;

    const float* adjrow = adj + ((size_t)(b * NN + r0 + pi)) * NN;
    const float* hw = h + (size_t)b * NN * HH + wid * 16;

    float acc[8][2][4];
#pragma unroll
    for (int m = 0; m < 8; m++)
#pragma unroll
        for (int n = 0; n < 2; n++)
#pragma unroll
            for (int e = 0; e < 4; e++) acc[m][n][e] = 0.f;

    float4 av[2];
#pragma unroll
    for (int q = 0; q < 2; q++)
        av[q] = *reinterpret_cast<const float4*>(adjrow + pq * 8 + q * 4);

    for (int tile = 0; tile < 32; tile++) {
        const int j0 = tile * 32;
        // produce P (mask + leaky + exp + tf32); s2 read straight from SMEM
#pragma unroll
        for (int q = 0; q < 2; q++) {
            float4 sq = *reinterpret_cast<const float4*>(s2f + j0 + pq * 8 + q * 4);
            const float* a = &av[q].x;
            const float* s = &sq.x;
            float p[4];
#pragma unroll
            for (int e = 0; e < 4; e++) {
                float z = my_s1 + s[e];
                float l = (z >= 0.f) ? z : 0.2f * z;
                float pv = (a[e] > 0.f) ? expf(l - my_m) : 0.f;
                rsum += pv;
                p[e] = pv;
            }
            uint4 u = make_uint4(to_tf32(p[0]), to_tf32(p[1]), to_tf32(p[2]), to_tf32(p[3]));
            *reinterpret_cast<uint4*>(&Ps[pi * 36 + pq * 8 + q * 4]) = u;
        }
        __syncthreads();

        if (tile + 1 < 32) {
            const int jn = j0 + 32;
#pragma unroll
            for (int q = 0; q < 2; q++)
                av[q] = *reinterpret_cast<const float4*>(adjrow + jn + pq * 8 + q * 4);
        }

        uint32_t bc[2][2], bn[2][2];
#pragma unroll
        for (int n = 0; n < 2; n++) {
            bc[n][0] = to_tf32(hw[(size_t)(j0 + tid4) * HH + n * 8 + g]);
            bc[n][1] = to_tf32(hw[(size_t)(j0 + tid4 + 4) * HH + n * 8 + g]);
        }
#pragma unroll
        for (int kk = 0; kk < 4; kk++) {
            if (kk < 3) {
                const int jr = j0 + (kk + 1) * 8;
#pragma unroll
                for (int n = 0; n < 2; n++) {
                    bn[n][0] = to_tf32(hw[(size_t)(jr + tid4) * HH + n * 8 + g]);
                    bn[n][1] = to_tf32(hw[(size_t)(jr + tid4 + 4) * HH + n * 8 + g]);
                }
            }
#pragma unroll
            for (int m = 0; m < 8; m++) {
                const int abase = (m * 16 + g) * 36 + kk * 8 + tid4;
                uint32_t a[4];
                a[0] = Ps[abase];
                a[1] = Ps[abase + 8 * 36];
                a[2] = Ps[abase + 4];
                a[3] = Ps[abase + 8 * 36 + 4];
#pragma unroll
                for (int n = 0; n < 2; n++) mma_tf32(acc[m][n], a, bc[n]);
            }
#pragma unroll
            for (int n = 0; n < 2; n++) { bc[n][0] = bn[n][0]; bc[n][1] = bn[n][1]; }
        }
        __syncthreads();
    }

    s_part[t] = rsum;
    __syncthreads();
    if (t < 128)
        s_inv[t] = 1.f / (s_part[4 * t] + s_part[4 * t + 1] + s_part[4 * t + 2] + s_part[4 * t + 3]);
    __syncthreads();

    float* ob = out + ((size_t)(b * NN + r0)) * HH + wid * 16;
#pragma unroll
    for (int m = 0; m < 8; m++) {
        const int rA = m * 16 + g, rB = rA + 8;
        const float invA = s_inv[rA], invB = s_inv[rB];
#pragma unroll
        for (int n = 0; n < 2; n++) {
            const int c = n * 8 + tid4 * 2;
            float2 vA = make_float2(fmaxf(acc[m][n][0] * invA, 0.f),
                                    fmaxf(acc[m][n][1] * invA, 0.f));
            float2 vB = make_float2(fmaxf(acc[m][n][2] * invB, 0.f),
                                    fmaxf(acc[m][n][3] * invB, 0.f));
            *reinterpret_cast<float2*>(ob + (size_t)rA * HH + c) = vA;
            *reinterpret_cast<float2*>(ob + (size_t)rB * HH + c) = vB;
        }
    }
}

// ---------------- pooling + MLP ----------------
__global__ void pool_k(const float* __restrict__ x, const float* __restrict__ W1,
                       const float* __restrict__ b1, const float* __restrict__ W2,
                       const float* __restrict__ b2, float* __restrict__ g) {
    __shared__ float g0s[HH];
    __shared__ float g1s[HH];
    const int t = threadIdx.x, b = blockIdx.x;
    const float* xb = x + b * NN * HH;
    float sum = 0.f, mx = -3.4e38f;
    for (int n = 0; n < NN; n++) {
        float v = xb[n * HH + t];
        sum += v;
        mx = fmaxf(mx, v);
    }
    g0s[t] = sum * (1.0f / NN) + mx;
    __syncthreads();
    float acc = b1[t];
#pragma unroll 8
    for (int k = 0; k < HH; k++) acc = fmaf(g0s[k], W1[k * HH + t], acc);
    g1s[t] = fmaxf(acc, 0.f);
    __syncthreads();
    float acc2 = b2[t];
#pragma unroll 8
    for (int k = 0; k < HH; k++) acc2 = fmaf(g1s[k], W2[k * HH + t], acc2);
    g[b * HH + t] = acc2;
}

extern "C" void kernel_launch(void* const* d_in, const int* in_sizes, int n_in,
                              void* d_out, int out_size) {
    const float* nf   = (const float*)d_in[0];
    const float* adj  = (const float*)d_in[1];
    const float* embW = (const float*)d_in[2];
    const float* embB = (const float*)d_in[3];
    const float* W0   = (const float*)d_in[4];
    const float* a1_0 = (const float*)d_in[5];
    const float* a2_0 = (const float*)d_in[6];
    const float* W1   = (const float*)d_in[7];
    const float* a1_1 = (const float*)d_in[8];
    const float* a2_1 = (const float*)d_in[9];
    const float* gW1  = (const float*)d_in[10];
    const float* gb1  = (const float*)d_in[11];
    const float* gW2  = (const float*)d_in[12];
    const float* gb2  = (const float*)d_in[13];
    float* out = (float*)d_out;

    float *xbuf, *hbuf, *s1, *s2;
    cudaGetSymbolAddress((void**)&xbuf, g_x);
    cudaGetSymbolAddress((void**)&hbuf, g_h);
    cudaGetSymbolAddress((void**)&s1, g_s1);
    cudaGetSymbolAddress((void**)&s2, g_s2);

    const int NB = BB * NN / 128;   // 128 blocks

    // embed: x = nf @ embW + embB
    mm_mma_k<FIN, true, false><<<NB, 512>>>(nf, embW, embB, nullptr, nullptr,
                                            xbuf, nullptr, nullptr);
    // layer 0: h = x @ W0, fused s1/s2
    mm_mma_k<HH, false, true><<<NB, 512>>>(xbuf, W0, nullptr, a1_0, a2_0,
                                           hbuf, s1, s2);
    attn_mma_k<<<dim3(NN / 128, BB), 512>>>(hbuf, adj, s1, s2, xbuf);
    // layer 1
    mm_mma_k<HH, false, true><<<NB, 512>>>(xbuf, W1, nullptr, a1_1, a2_1,
                                           hbuf, s1, s2);
    attn_mma_k<<<dim3(NN / 128, BB), 512>>>(hbuf, adj, s1, s2, out);

    pool_k<<<BB, 512 / 2>>>(out, gW1, gb1, gW2, gb2, out + BB * NN * HH);
}